// round 5
// baseline (speedup 1.0000x reference)
#include <cuda_runtime.h>

#define NT 256
typedef unsigned long long u64;

// MASKS[ph][q] = F^{-1} e_q (partner-flip mask); ROWSF[ph][q] = row q of frame F.
constexpr int MASKS[3][12] = {
  {0x800,0x400,0x200,0x100,0x080,0x040,0x020,0x010,0x008,0x004,0x002,0x001},
  {0xC00,0x600,0x300,0x180,0x0C0,0x060,0x030,0x018,0x00C,0x006,0x003,0x001},
  {0xA00,0x500,0x280,0x140,0x0A0,0x050,0x028,0x014,0x00A,0x005,0x002,0x001}};
constexpr int ROWSF[3][12] = {
  {0x800,0x400,0x200,0x100,0x080,0x040,0x020,0x010,0x008,0x004,0x002,0x001},
  {0x800,0xC00,0xE00,0xF00,0xF80,0xFC0,0xFE0,0xFF0,0xFF8,0xFFC,0xFFE,0xFFF},
  {0x800,0x400,0xA00,0x500,0xA80,0x540,0xAA0,0x550,0xAA8,0x554,0xAAA,0x555}};

// Device-visible copy of the frame-C^2 rows for the readout sign computation.
__device__ __constant__ int ROWS2[12] =
  {0x800,0x400,0xA00,0x500,0xA80,0x540,0xAA0,0x550,0xAA8,0x554,0xAAA,0x555};

__host__ __device__ constexpr int SWc(int i) { return i ^ (i >> 3); }
__device__ __forceinline__ int SW(int i) { return i ^ (i >> 3); }

// ---- packed f32x2 helpers (re in low word, im in high word) ----
__device__ __forceinline__ u64 pk(float x, float y) {
    u64 r; asm("mov.b64 %0,{%1,%2};" : "=l"(r) : "f"(x), "f"(y)); return r;
}
__device__ __forceinline__ void upk(u64 v, float& x, float& y) {
    asm("mov.b64 {%0,%1},%2;" : "=f"(x), "=f"(y) : "l"(v));
}
__device__ __forceinline__ u64 swp(u64 v) { float x, y; upk(v, x, y); return pk(y, x); }
__device__ __forceinline__ u64 fma2(u64 a, u64 b, u64 c) {
    u64 r; asm("fma.rn.f32x2 %0,%1,%2,%3;" : "=l"(r) : "l"(a), "l"(b), "l"(c)); return r;
}
__device__ __forceinline__ u64 mul2(u64 a, u64 b) {
    u64 r; asm("mul.rn.f32x2 %0,%1,%2;" : "=l"(r) : "l"(a), "l"(b)); return r;
}
__device__ __forceinline__ u64 add2(u64 a, u64 b) {
    u64 r; asm("add.rn.f32x2 %0,%1,%2;" : "=l"(r) : "l"(a), "l"(b)); return r;
}

__device__ __forceinline__ float2 cmul(float2 a, float2 b) {
    return make_float2(fmaf(a.x, b.x, -a.y * b.y), fmaf(a.x, b.y, a.y * b.x));
}
__device__ __forceinline__ float2 loF(float4 v) { return make_float2(v.x, v.y); }
__device__ __forceinline__ float2 hiF(float4 v) { return make_float2(v.z, v.w); }

// Gate (special form): n0 = a*w0 + b*w1 ; n1 = ph * (-b*w0 + a*w1)
// REAL variant: ph == 1 (diagonal phase dropped) -> 4 packed ops, no swap.
struct GateP { u64 aa, bb, nb, px, py; };
template<bool REAL>
__device__ __forceinline__ GateP mkgate(float4 g) {
    GateP G;
    G.aa = pk(g.x, g.x);  G.bb = pk(g.y, g.y);  G.nb = pk(-g.y, -g.y);
    if (!REAL) { G.px = pk(g.z, g.z);  G.py = pk(-g.w, g.w); }
    return G;
}
template<bool REAL>
__device__ __forceinline__ void gp(u64& w0, u64& w1, const GateP& G) {
    u64 n0 = fma2(G.aa, w0, mul2(G.bb, w1));
    u64 t  = fma2(G.nb, w0, mul2(G.aa, w1));
    w1 = REAL ? t : fma2(G.py, swp(t), mul2(G.px, t));   // ph * t (complex)
    w0 = n0;
}

// One sweep applying 4 gates (qubits Q0..Q0+3) in frame PH. Each thread owns
// exactly one 16-amp coset. Returns normalized base index b000 (logical bits 0).
template<int PH, int Q0, bool WB, bool REAL>
__device__ __forceinline__ int pass4(u64* s, const float4* gt, int p, u64* w) {
    constexpr int mA = MASKS[PH][Q0+0], mB = MASKS[PH][Q0+1];
    constexpr int mC = MASKS[PH][Q0+2], mD = MASKS[PH][Q0+3];
    constexpr int rA = ROWSF[PH][Q0+0], rB = ROWSF[PH][Q0+1];
    constexpr int rC = ROWSF[PH][Q0+2], rD = ROWSF[PH][Q0+3];
    constexpr int sh = 8 - Q0;
    constexpr int sA = SWc(mA), sB = SWc(mB), sC = SWc(mC), sD = SWc(mD);

    int low  = p & ((1 << sh) - 1);
    int base = ((p >> sh) << (sh + 4)) | low;      // pivot bits zero
    int b000 = base;                                // normalize logical bits to 0
    if (__popc(base & rA) & 1) b000 ^= mA;
    if (__popc(base & rB) & 1) b000 ^= mB;
    if (__popc(base & rC) & 1) b000 ^= mC;
    if (__popc(base & rD) & 1) b000 ^= mD;
    const int a0 = SW(b000);

    #pragma unroll
    for (int i = 0; i < 16; i++) {
        int off = ((i & 8) ? sA : 0) ^ ((i & 4) ? sB : 0) ^ ((i & 2) ? sC : 0) ^ ((i & 1) ? sD : 0);
        w[i] = s[a0 ^ off];
    }
    {   GateP G = mkgate<REAL>(gt[Q0 + 0]);
        #pragma unroll
        for (int i = 0; i < 8; i++) gp<REAL>(w[i], w[i + 8], G); }
    {   GateP G = mkgate<REAL>(gt[Q0 + 1]);
        #pragma unroll
        for (int i = 0; i < 16; i++) if (!(i & 4)) gp<REAL>(w[i], w[i + 4], G); }
    {   GateP G = mkgate<REAL>(gt[Q0 + 2]);
        #pragma unroll
        for (int i = 0; i < 16; i++) if (!(i & 2)) gp<REAL>(w[i], w[i + 2], G); }
    {   GateP G = mkgate<REAL>(gt[Q0 + 3]);
        #pragma unroll
        for (int i = 0; i < 16; i++) if (!(i & 1)) gp<REAL>(w[i], w[i + 1], G); }
    if (WB) {
        #pragma unroll
        for (int i = 0; i < 16; i++) {
            int off = ((i & 8) ? sA : 0) ^ ((i & 4) ? sB : 0) ^ ((i & 2) ? sC : 0) ^ ((i & 1) ? sD : 0);
            s[a0 ^ off] = w[i];
        }
    }
    return b000;
}

__global__ void __launch_bounds__(NT, 4)
vqc_kernel(const float* __restrict__ inputs,
           const float* __restrict__ thetas,
           float* __restrict__ out) {
    __shared__ float2 st[4096];
    __shared__ float4 vtab[12];   // column-0 of merged (enc + ansatz-L0) gate
    __shared__ float4 gtab[24];   // L1, L2 gate params (a, b, ph.x, ph.y)
    __shared__ u64   part[8][6];  // per-warp packed readout partials
    u64* s = reinterpret_cast<u64*>(st);

    const int tid = threadIdx.x;
    const int b   = blockIdx.x;

    // ---- per-qubit coefficients ----
    if (tid < 12) {
        int q = tid;
        float x  = inputs[b * 12 + q];
        float ty = thetas[2 * q], tz = thetas[2 * q + 1];
        float sx, cx, sy, cy, sz, cz;
        sincospif(x, &sx, &cx);            // e^{i pi x}
        sincospif(0.5f * ty, &sy, &cy);    // Y^ty entries
        sincospif(tz, &sz, &cz);           // e^{i pi tz}
        const float r = 0.70710678118654752f;
        // v = Z^tz * Y^ty * Z^x * H * (1,0)^T
        float v0x = r * (cy - sy * cx), v0y = -r * sy * sx;
        float tx = sy + cy * cx, tw = cy * sx;
        float v1x = r * (cz * tx - sz * tw), v1y = r * (cz * tw + sz * tx);
        vtab[q] = make_float4(v0x, v0y, v1x, v1y);
    } else if (tid < 36) {
        int idx = tid - 12;                 // (layer-1)*12 + q
        int l = idx / 12 + 1, q = idx % 12;
        float ty = thetas[l * 24 + 2 * q], tz = thetas[l * 24 + 2 * q + 1];
        float sy, cy, sz, cz;
        sincospif(0.5f * ty, &sy, &cy);
        sincospif(tz, &sz, &cz);
        // Layer 2 (idx >= 12): Z^tz is diagonal and unobservable in |amp|^2 -> drop.
        gtab[idx] = make_float4(cy, -sy, cz, sz);
    }
    __syncthreads();

    // ---- init: product state after merged (enc + L0) layer, frame 0 ----
    {
        float4 v0q = vtab[0];
        float2 f = ((tid >> 7) & 1) ? hiF(v0q) : loF(v0q);
        #pragma unroll
        for (int q = 1; q < 8; q++) {
            float4 v = vtab[q];
            f = cmul(f, ((tid >> (7 - q)) & 1) ? hiF(v) : loF(v));
        }
        float4 v8 = vtab[8], v9 = vtab[9], vA = vtab[10], vB = vtab[11];
        float2 t8[2], t9[4], tA[8];
        t8[0] = cmul(f, loF(v8));  t8[1] = cmul(f, hiF(v8));
        #pragma unroll
        for (int j = 0; j < 2; j++) { t9[2*j] = cmul(t8[j], loF(v9)); t9[2*j+1] = cmul(t8[j], hiF(v9)); }
        #pragma unroll
        for (int j = 0; j < 4; j++) { tA[2*j] = cmul(t9[j], loF(vA)); tA[2*j+1] = cmul(t9[j], hiF(vA)); }
        #pragma unroll
        for (int l = 0; l < 16; l++) {
            float2 amp = cmul(tA[l >> 1], (l & 1) ? hiF(vB) : loF(vB));
            st[SW((tid << 4) | l)] = amp;
        }
    }
    __syncthreads();

    // ---- ansatz layers 1 (frame C, complex) and 2 (frame C^2, real: Z dropped) ----
    u64 w[16];
    pass4<1, 0, true,  false>(s, gtab,      tid, w); __syncthreads();
    pass4<1, 4, true,  false>(s, gtab,      tid, w); __syncthreads();
    pass4<1, 8, true,  false>(s, gtab,      tid, w); __syncthreads();
    pass4<2, 0, true,  true >(s, gtab + 12, tid, w); __syncthreads();
    pass4<2, 4, true,  true >(s, gtab + 12, tid, w); __syncthreads();
    int b000 = pass4<2, 8, false, true>(s, gtab + 12, tid, w);  // fused with readout

    // ---- readout directly from registers ----
    // q=0..7: sign depends only on b000; q=8..11: single-axis WHT components.
    float S = 0.f, d3 = 0.f, d2 = 0.f, d1 = 0.f, d0 = 0.f;
    #pragma unroll
    for (int i = 0; i < 16; i++) {
        float x, y; upk(w[i], x, y);
        float pr = fmaf(x, x, y * y);
        S += pr;
        d3 = (i & 8) ? d3 - pr : d3 + pr;
        d2 = (i & 4) ? d2 - pr : d2 + pr;
        d1 = (i & 2) ? d1 - pr : d1 + pr;
        d0 = (i & 1) ? d0 - pr : d0 + pr;
    }
    // pack the 12 signed accumulators into 6 u64 lanes
    u64 acc[6];
    {
        float av[12];
        #pragma unroll
        for (int q = 0; q < 12; q++) {
            float v = (q < 8) ? S : (q == 8) ? d3 : (q == 9) ? d2 : (q == 10) ? d1 : d0;
            av[q] = (__popc(b000 & ROWS2[q]) & 1) ? -v : v;
        }
        #pragma unroll
        for (int j = 0; j < 6; j++) acc[j] = pk(av[2*j], av[2*j+1]);
    }
    #pragma unroll
    for (int o = 16; o; o >>= 1) {
        #pragma unroll
        for (int j = 0; j < 6; j++)
            acc[j] = add2(acc[j], __shfl_xor_sync(0xffffffffu, acc[j], o));
    }
    if ((tid & 31) == 0) {
        #pragma unroll
        for (int j = 0; j < 6; j++) part[tid >> 5][j] = acc[j];
    }
    __syncthreads();
    if (tid < 12) {
        const float* pf = reinterpret_cast<const float*>(part);
        float r0 = 0.f;
        #pragma unroll
        for (int wgt = 0; wgt < 8; wgt++) r0 += pf[wgt * 12 + tid];
        out[b * 12 + tid] = r0;
    }
}

extern "C" void kernel_launch(void* const* d_in, const int* in_sizes, int n_in,
                              void* d_out, int out_size) {
    const float* inputs = (const float*)d_in[0];   // [1024, 12] f32
    const float* thetas = (const float*)d_in[1];   // [72] f32
    float* out = (float*)d_out;                    // [1024, 12] f32
    vqc_kernel<<<1024, NT>>>(inputs, thetas, out);
}

// round 6
// speedup vs baseline: 1.5381x; 1.5381x over previous
#include <cuda_runtime.h>

#define NT 256
typedef unsigned long long u64;

// MASKS[ph][q] = F^{-1} e_q (partner-flip mask); ROWSF[ph][q] = row q of frame F.
constexpr int MASKS[3][12] = {
  {0x800,0x400,0x200,0x100,0x080,0x040,0x020,0x010,0x008,0x004,0x002,0x001},
  {0xC00,0x600,0x300,0x180,0x0C0,0x060,0x030,0x018,0x00C,0x006,0x003,0x001},
  {0xA00,0x500,0x280,0x140,0x0A0,0x050,0x028,0x014,0x00A,0x005,0x002,0x001}};
constexpr int ROWSF[3][12] = {
  {0x800,0x400,0x200,0x100,0x080,0x040,0x020,0x010,0x008,0x004,0x002,0x001},
  {0x800,0xC00,0xE00,0xF00,0xF80,0xFC0,0xFE0,0xFF0,0xFF8,0xFFC,0xFFE,0xFFF},
  {0x800,0x400,0xA00,0x500,0xA80,0x540,0xAA0,0x550,0xAA8,0x554,0xAAA,0x555}};

// Device-visible copy of the frame-C^2 rows for the readout sign computation.
__device__ __constant__ int ROWS2[12] =
  {0x800,0x400,0xA00,0x500,0xA80,0x540,0xAA0,0x550,0xAA8,0x554,0xAAA,0x555};

__host__ __device__ constexpr int SWc(int i) { return i ^ (i >> 3); }
__device__ __forceinline__ int SW(int i) { return i ^ (i >> 3); }

// ---- packed f32x2 helpers (re in low word, im in high word) ----
__device__ __forceinline__ u64 pk(float x, float y) {
    u64 r; asm("mov.b64 %0,{%1,%2};" : "=l"(r) : "f"(x), "f"(y)); return r;
}
__device__ __forceinline__ void upk(u64 v, float& x, float& y) {
    asm("mov.b64 {%0,%1},%2;" : "=f"(x), "=f"(y) : "l"(v));
}
__device__ __forceinline__ u64 swp(u64 v) { float x, y; upk(v, x, y); return pk(y, x); }
__device__ __forceinline__ u64 fma2(u64 a, u64 b, u64 c) {
    u64 r; asm("fma.rn.f32x2 %0,%1,%2,%3;" : "=l"(r) : "l"(a), "l"(b), "l"(c)); return r;
}
__device__ __forceinline__ u64 mul2(u64 a, u64 b) {
    u64 r; asm("mul.rn.f32x2 %0,%1,%2;" : "=l"(r) : "l"(a), "l"(b)); return r;
}
__device__ __forceinline__ u64 add2(u64 a, u64 b) {
    u64 r; asm("add.rn.f32x2 %0,%1,%2;" : "=l"(r) : "l"(a), "l"(b)); return r;
}

__device__ __forceinline__ float2 cmul(float2 a, float2 b) {
    return make_float2(fmaf(a.x, b.x, -a.y * b.y), fmaf(a.x, b.y, a.y * b.x));
}
__device__ __forceinline__ float2 loF(float4 v) { return make_float2(v.x, v.y); }
__device__ __forceinline__ float2 hiF(float4 v) { return make_float2(v.z, v.w); }

// Gate (special form): n0 = a*w0 + b*w1 ; n1 = ph * (-b*w0 + a*w1)
// REAL variant: ph == 1 (diagonal phase dropped) -> 4 packed ops, no swap.
struct GateP { u64 aa, bb, nb, px, py; };
template<bool REAL>
__device__ __forceinline__ GateP mkgate(float4 g) {
    GateP G;
    G.aa = pk(g.x, g.x);  G.bb = pk(g.y, g.y);  G.nb = pk(-g.y, -g.y);
    if (!REAL) { G.px = pk(g.z, g.z);  G.py = pk(-g.w, g.w); }
    return G;
}
template<bool REAL>
__device__ __forceinline__ void gp(u64& w0, u64& w1, const GateP& G) {
    u64 n0 = fma2(G.aa, w0, mul2(G.bb, w1));
    u64 t  = fma2(G.nb, w0, mul2(G.aa, w1));
    w1 = REAL ? t : fma2(G.py, swp(t), mul2(G.px, t));   // ph * t (complex)
    w0 = n0;
}

// One sweep applying 4 gates (qubits Q0..Q0+3) in frame PH. Each thread owns
// exactly one 16-amp coset. Returns normalized base index b000 (logical bits 0).
template<int PH, int Q0, bool WB, bool REAL>
__device__ __forceinline__ int pass4(u64* s, const float4* gt, int p, u64* w) {
    constexpr int mA = MASKS[PH][Q0+0], mB = MASKS[PH][Q0+1];
    constexpr int mC = MASKS[PH][Q0+2], mD = MASKS[PH][Q0+3];
    constexpr int rA = ROWSF[PH][Q0+0], rB = ROWSF[PH][Q0+1];
    constexpr int rC = ROWSF[PH][Q0+2], rD = ROWSF[PH][Q0+3];
    constexpr int sh = 8 - Q0;
    constexpr int sA = SWc(mA), sB = SWc(mB), sC = SWc(mC), sD = SWc(mD);

    int low  = p & ((1 << sh) - 1);
    int base = ((p >> sh) << (sh + 4)) | low;      // pivot bits zero
    int b000 = base;                                // normalize logical bits to 0
    if (__popc(base & rA) & 1) b000 ^= mA;
    if (__popc(base & rB) & 1) b000 ^= mB;
    if (__popc(base & rC) & 1) b000 ^= mC;
    if (__popc(base & rD) & 1) b000 ^= mD;
    const int a0 = SW(b000);

    #pragma unroll
    for (int i = 0; i < 16; i++) {
        int off = ((i & 8) ? sA : 0) ^ ((i & 4) ? sB : 0) ^ ((i & 2) ? sC : 0) ^ ((i & 1) ? sD : 0);
        w[i] = s[a0 ^ off];
    }
    {   GateP G = mkgate<REAL>(gt[Q0 + 0]);
        #pragma unroll
        for (int i = 0; i < 8; i++) gp<REAL>(w[i], w[i + 8], G); }
    {   GateP G = mkgate<REAL>(gt[Q0 + 1]);
        #pragma unroll
        for (int i = 0; i < 16; i++) if (!(i & 4)) gp<REAL>(w[i], w[i + 4], G); }
    {   GateP G = mkgate<REAL>(gt[Q0 + 2]);
        #pragma unroll
        for (int i = 0; i < 16; i++) if (!(i & 2)) gp<REAL>(w[i], w[i + 2], G); }
    {   GateP G = mkgate<REAL>(gt[Q0 + 3]);
        #pragma unroll
        for (int i = 0; i < 16; i++) if (!(i & 1)) gp<REAL>(w[i], w[i + 1], G); }
    if (WB) {
        #pragma unroll
        for (int i = 0; i < 16; i++) {
            int off = ((i & 8) ? sA : 0) ^ ((i & 4) ? sB : 0) ^ ((i & 2) ? sC : 0) ^ ((i & 1) ? sD : 0);
            s[a0 ^ off] = w[i];
        }
    }
    return b000;
}

__global__ void __launch_bounds__(NT)
vqc_kernel(const float* __restrict__ inputs,
           const float* __restrict__ thetas,
           float* __restrict__ out) {
    __shared__ float2 st[4096];
    __shared__ float4 vtab[12];   // column-0 of merged (enc + ansatz-L0) gate
    __shared__ float4 gtab[24];   // L1, L2 gate params (a, b, ph.x, ph.y)
    __shared__ u64   part[8][6];  // per-warp packed readout partials
    u64* s = reinterpret_cast<u64*>(st);

    const int tid = threadIdx.x;
    const int b   = blockIdx.x;

    // ---- per-qubit coefficients ----
    if (tid < 12) {
        int q = tid;
        float x  = inputs[b * 12 + q];
        float ty = thetas[2 * q], tz = thetas[2 * q + 1];
        float sx, cx, sy, cy, sz, cz;
        sincospif(x, &sx, &cx);            // e^{i pi x}
        sincospif(0.5f * ty, &sy, &cy);    // Y^ty entries
        sincospif(tz, &sz, &cz);           // e^{i pi tz}
        const float r = 0.70710678118654752f;
        // v = Z^tz * Y^ty * Z^x * H * (1,0)^T
        float v0x = r * (cy - sy * cx), v0y = -r * sy * sx;
        float tx = sy + cy * cx, tw = cy * sx;
        float v1x = r * (cz * tx - sz * tw), v1y = r * (cz * tw + sz * tx);
        vtab[q] = make_float4(v0x, v0y, v1x, v1y);
    } else if (tid < 36) {
        int idx = tid - 12;                 // (layer-1)*12 + q
        int l = idx / 12 + 1, q = idx % 12;
        float ty = thetas[l * 24 + 2 * q], tz = thetas[l * 24 + 2 * q + 1];
        float sy, cy, sz, cz;
        sincospif(0.5f * ty, &sy, &cy);
        sincospif(tz, &sz, &cz);
        // Layer 2 (idx >= 12): Z^tz is diagonal and unobservable in |amp|^2 -> kept
        // in the table but ignored by the REAL passes.
        gtab[idx] = make_float4(cy, -sy, cz, sz);
    }
    __syncthreads();

    // ---- init: product state after merged (enc + L0) layer, frame 0 ----
    {
        float4 v0q = vtab[0];
        float2 f = ((tid >> 7) & 1) ? hiF(v0q) : loF(v0q);
        #pragma unroll
        for (int q = 1; q < 8; q++) {
            float4 v = vtab[q];
            f = cmul(f, ((tid >> (7 - q)) & 1) ? hiF(v) : loF(v));
        }
        float4 v8 = vtab[8], v9 = vtab[9], vA = vtab[10], vB = vtab[11];
        float2 t8[2], t9[4], tA[8];
        t8[0] = cmul(f, loF(v8));  t8[1] = cmul(f, hiF(v8));
        #pragma unroll
        for (int j = 0; j < 2; j++) { t9[2*j] = cmul(t8[j], loF(v9)); t9[2*j+1] = cmul(t8[j], hiF(v9)); }
        #pragma unroll
        for (int j = 0; j < 4; j++) { tA[2*j] = cmul(t9[j], loF(vA)); tA[2*j+1] = cmul(t9[j], hiF(vA)); }
        #pragma unroll
        for (int l = 0; l < 16; l++) {
            float2 amp = cmul(tA[l >> 1], (l & 1) ? hiF(vB) : loF(vB));
            st[SW((tid << 4) | l)] = amp;
        }
    }
    __syncthreads();

    // ---- ansatz layers 1 (frame C, complex) and 2 (frame C^2, real: Z dropped) ----
    u64 w[16];
    pass4<1, 0, true,  false>(s, gtab,      tid, w); __syncthreads();
    pass4<1, 4, true,  false>(s, gtab,      tid, w); __syncthreads();
    pass4<1, 8, true,  false>(s, gtab,      tid, w); __syncthreads();
    pass4<2, 0, true,  true >(s, gtab + 12, tid, w); __syncthreads();
    pass4<2, 4, true,  true >(s, gtab + 12, tid, w); __syncthreads();
    int b000 = pass4<2, 8, false, true>(s, gtab + 12, tid, w);  // fused with readout

    // ---- readout directly from registers ----
    // q=0..7: sign depends only on b000; q=8..11: single-axis WHT components.
    float S = 0.f, d3 = 0.f, d2 = 0.f, d1 = 0.f, d0 = 0.f;
    #pragma unroll
    for (int i = 0; i < 16; i++) {
        float x, y; upk(w[i], x, y);
        float pr = fmaf(x, x, y * y);
        S += pr;
        d3 = (i & 8) ? d3 - pr : d3 + pr;
        d2 = (i & 4) ? d2 - pr : d2 + pr;
        d1 = (i & 2) ? d1 - pr : d1 + pr;
        d0 = (i & 1) ? d0 - pr : d0 + pr;
    }
    // pack the 12 signed accumulators into 6 u64 lanes
    u64 acc[6];
    {
        float av[12];
        #pragma unroll
        for (int q = 0; q < 12; q++) {
            float v = (q < 8) ? S : (q == 8) ? d3 : (q == 9) ? d2 : (q == 10) ? d1 : d0;
            av[q] = (__popc(b000 & ROWS2[q]) & 1) ? -v : v;
        }
        #pragma unroll
        for (int j = 0; j < 6; j++) acc[j] = pk(av[2*j], av[2*j+1]);
    }
    #pragma unroll
    for (int o = 16; o; o >>= 1) {
        #pragma unroll
        for (int j = 0; j < 6; j++)
            acc[j] = add2(acc[j], __shfl_xor_sync(0xffffffffu, acc[j], o));
    }
    if ((tid & 31) == 0) {
        #pragma unroll
        for (int j = 0; j < 6; j++) part[tid >> 5][j] = acc[j];
    }
    __syncthreads();
    if (tid < 12) {
        const float* pf = reinterpret_cast<const float*>(part);
        float r0 = 0.f;
        #pragma unroll
        for (int wgt = 0; wgt < 8; wgt++) r0 += pf[wgt * 12 + tid];
        out[b * 12 + tid] = r0;
    }
}

extern "C" void kernel_launch(void* const* d_in, const int* in_sizes, int n_in,
                              void* d_out, int out_size) {
    const float* inputs = (const float*)d_in[0];   // [1024, 12] f32
    const float* thetas = (const float*)d_in[1];   // [72] f32
    float* out = (float*)d_out;                    // [1024, 12] f32
    vqc_kernel<<<1024, NT>>>(inputs, thetas, out);
}

// round 7
// speedup vs baseline: 1.5582x; 1.0131x over previous
#include <cuda_runtime.h>

#define NT 256
typedef unsigned long long u64;

// MASKS[ph][q] = F^{-1} e_q (partner-flip mask); ROWSF[ph][q] = row q of frame F.
constexpr int MASKS[3][12] = {
  {0x800,0x400,0x200,0x100,0x080,0x040,0x020,0x010,0x008,0x004,0x002,0x001},
  {0xC00,0x600,0x300,0x180,0x0C0,0x060,0x030,0x018,0x00C,0x006,0x003,0x001},
  {0xA00,0x500,0x280,0x140,0x0A0,0x050,0x028,0x014,0x00A,0x005,0x002,0x001}};
constexpr int ROWSF[3][12] = {
  {0x800,0x400,0x200,0x100,0x080,0x040,0x020,0x010,0x008,0x004,0x002,0x001},
  {0x800,0xC00,0xE00,0xF00,0xF80,0xFC0,0xFE0,0xFF0,0xFF8,0xFFC,0xFFE,0xFFF},
  {0x800,0x400,0xA00,0x500,0xA80,0x540,0xAA0,0x550,0xAA8,0x554,0xAAA,0x555}};

// Device-visible copy of the frame-C^2 rows for the readout sign computation.
__device__ __constant__ int ROWS2[12] =
  {0x800,0x400,0xA00,0x500,0xA80,0x540,0xAA0,0x550,0xAA8,0x554,0xAAA,0x555};

__host__ __device__ constexpr int SWc(int i) { return i ^ (i >> 3); }
__device__ __forceinline__ int SW(int i) { return i ^ (i >> 3); }

// ---- packed f32x2 helpers (re in low word, im in high word) ----
__device__ __forceinline__ u64 pk(float x, float y) {
    u64 r; asm("mov.b64 %0,{%1,%2};" : "=l"(r) : "f"(x), "f"(y)); return r;
}
__device__ __forceinline__ void upk(u64 v, float& x, float& y) {
    asm("mov.b64 {%0,%1},%2;" : "=f"(x), "=f"(y) : "l"(v));
}
__device__ __forceinline__ u64 swp(u64 v) { float x, y; upk(v, x, y); return pk(y, x); }
__device__ __forceinline__ u64 fma2(u64 a, u64 b, u64 c) {
    u64 r; asm("fma.rn.f32x2 %0,%1,%2,%3;" : "=l"(r) : "l"(a), "l"(b), "l"(c)); return r;
}
__device__ __forceinline__ u64 mul2(u64 a, u64 b) {
    u64 r; asm("mul.rn.f32x2 %0,%1,%2;" : "=l"(r) : "l"(a), "l"(b)); return r;
}
__device__ __forceinline__ u64 add2(u64 a, u64 b) {
    u64 r; asm("add.rn.f32x2 %0,%1,%2;" : "=l"(r) : "l"(a), "l"(b)); return r;
}

__device__ __forceinline__ float2 cmul(float2 a, float2 b) {
    return make_float2(fmaf(a.x, b.x, -a.y * b.y), fmaf(a.x, b.y, a.y * b.x));
}
__device__ __forceinline__ float2 loF(float4 v) { return make_float2(v.x, v.y); }
__device__ __forceinline__ float2 hiF(float4 v) { return make_float2(v.z, v.w); }

// Gate (special form): n0 = a*w0 + b*w1 ; n1 = ph * (-b*w0 + a*w1)
// REAL variant: ph == 1 (diagonal phase dropped) -> 4 packed ops, no swap.
struct GateP { u64 aa, bb, nb, px, py; };
template<bool REAL>
__device__ __forceinline__ GateP mkgate(float4 g) {
    GateP G;
    G.aa = pk(g.x, g.x);  G.bb = pk(g.y, g.y);  G.nb = pk(-g.y, -g.y);
    if (!REAL) { G.px = pk(g.z, g.z);  G.py = pk(-g.w, g.w); }
    return G;
}
template<bool REAL>
__device__ __forceinline__ void gp(u64& w0, u64& w1, const GateP& G) {
    u64 n0 = fma2(G.aa, w0, mul2(G.bb, w1));
    u64 t  = fma2(G.nb, w0, mul2(G.aa, w1));
    w1 = REAL ? t : fma2(G.py, swp(t), mul2(G.px, t));   // ph * t (complex)
    w0 = n0;
}
// Real rotation with explicit (bb, nb) selection (for role-flipped gates).
__device__ __forceinline__ void gpsel(u64& w0, u64& w1, u64 aa, u64 bb, u64 nb) {
    u64 n0 = fma2(aa, w0, mul2(bb, w1));
    u64 t  = fma2(nb, w0, mul2(aa, w1));
    w0 = n0; w1 = t;
}

// One sweep applying 4 gates (qubits Q0..Q0+3) in frame PH. Each thread owns
// exactly one 16-amp coset. Returns normalized base index b000 (logical bits 0).
template<int PH, int Q0, bool WB, bool REAL>
__device__ __forceinline__ int pass4(u64* s, const float4* gt, int p, u64* w) {
    constexpr int mA = MASKS[PH][Q0+0], mB = MASKS[PH][Q0+1];
    constexpr int mC = MASKS[PH][Q0+2], mD = MASKS[PH][Q0+3];
    constexpr int rA = ROWSF[PH][Q0+0], rB = ROWSF[PH][Q0+1];
    constexpr int rC = ROWSF[PH][Q0+2], rD = ROWSF[PH][Q0+3];
    constexpr int sh = 8 - Q0;
    constexpr int sA = SWc(mA), sB = SWc(mB), sC = SWc(mC), sD = SWc(mD);

    int low  = p & ((1 << sh) - 1);
    int base = ((p >> sh) << (sh + 4)) | low;      // pivot bits zero
    int b000 = base;                                // normalize logical bits to 0
    if (__popc(base & rA) & 1) b000 ^= mA;
    if (__popc(base & rB) & 1) b000 ^= mB;
    if (__popc(base & rC) & 1) b000 ^= mC;
    if (__popc(base & rD) & 1) b000 ^= mD;
    const int a0 = SW(b000);

    #pragma unroll
    for (int i = 0; i < 16; i++) {
        int off = ((i & 8) ? sA : 0) ^ ((i & 4) ? sB : 0) ^ ((i & 2) ? sC : 0) ^ ((i & 1) ? sD : 0);
        w[i] = s[a0 ^ off];
    }
    {   GateP G = mkgate<REAL>(gt[Q0 + 0]);
        #pragma unroll
        for (int i = 0; i < 8; i++) gp<REAL>(w[i], w[i + 8], G); }
    {   GateP G = mkgate<REAL>(gt[Q0 + 1]);
        #pragma unroll
        for (int i = 0; i < 16; i++) if (!(i & 4)) gp<REAL>(w[i], w[i + 4], G); }
    {   GateP G = mkgate<REAL>(gt[Q0 + 2]);
        #pragma unroll
        for (int i = 0; i < 16; i++) if (!(i & 2)) gp<REAL>(w[i], w[i + 2], G); }
    {   GateP G = mkgate<REAL>(gt[Q0 + 3]);
        #pragma unroll
        for (int i = 0; i < 16; i++) if (!(i & 1)) gp<REAL>(w[i], w[i + 1], G); }
    if (WB) {
        #pragma unroll
        for (int i = 0; i < 16; i++) {
            int off = ((i & 8) ? sA : 0) ^ ((i & 4) ? sB : 0) ^ ((i & 2) ? sC : 0) ^ ((i & 1) ? sD : 0);
            s[a0 ^ off] = w[i];
        }
    }
    return b000;
}

// Fused pass: L1 gates on frame-C qubits 8-11 (complex) immediately followed by
// L2 gates on frame-C^2 qubits 8-11 (real). Both mask sets span bits 0-3, so the
// same 16-amp register coset covers both. Register layout uses L1 normalization;
// L2 role bits are handled by swapping (bb, nb) — a role-flipped real rotation is
// its transpose, i.e. b -> -b. g1/g2 are the L1/L2 gate tables.
__device__ __forceinline__ void pass_fused(u64* s, const float4* g1,
                                           const float4* g2, int p, u64* w) {
    // L1 constants (PH=1, Q0=8): masks {0xC,6,3,1}, rows {0xFF8,0xFFC,0xFFE,0xFFF}
    constexpr int sA = SWc(0xC), sB = SWc(0x6), sC = SWc(0x3), sD = SWc(0x1);
    int base = p << 4;
    int b000 = base;
    if (__popc(base & 0xFF8) & 1) b000 ^= 0xC;
    if (__popc(base & 0xFFC) & 1) b000 ^= 0x6;
    if (__popc(base & 0xFFE) & 1) b000 ^= 0x3;
    if (__popc(base & 0xFFF) & 1) b000 ^= 0x1;
    const int a0 = SW(b000);

    #pragma unroll
    for (int i = 0; i < 16; i++) {
        int off = ((i & 8) ? sA : 0) ^ ((i & 4) ? sB : 0) ^ ((i & 2) ? sC : 0) ^ ((i & 1) ? sD : 0);
        w[i] = s[a0 ^ off];
    }
    // ---- L1 q8-11, complex ----
    {   GateP G = mkgate<false>(g1[8]);
        #pragma unroll
        for (int i = 0; i < 8; i++) gp<false>(w[i], w[i + 8], G); }
    {   GateP G = mkgate<false>(g1[9]);
        #pragma unroll
        for (int i = 0; i < 16; i++) if (!(i & 4)) gp<false>(w[i], w[i + 4], G); }
    {   GateP G = mkgate<false>(g1[10]);
        #pragma unroll
        for (int i = 0; i < 16; i++) if (!(i & 2)) gp<false>(w[i], w[i + 2], G); }
    {   GateP G = mkgate<false>(g1[11]);
        #pragma unroll
        for (int i = 0; i < 16; i++) if (!(i & 1)) gp<false>(w[i], w[i + 1], G); }
    // ---- L2 q8-11, real, via role-flip machinery ----
    // Reg-space pair masks: m2 expressed in L1-mask basis:
    //   q8: 0xA=0xC^0x6 -> Delta=0b1100; q9: 0x5=0x6^0x3 -> 0b0110;
    //   q10: 0x2=0x3^0x1 -> 0b0011;     q11: 0x1        -> 0b0001.
    // Role fn: role(i) = F ^ parity(g_bits & i) with F = parity(r2 & b000).
    const int F8  = __popc(b000 & 0xAA8) & 1;
    const int F9  = __popc(b000 & 0x554) & 1;
    const int F10 = __popc(b000 & 0xAAA) & 1;
    const int F11 = __popc(b000 & 0x555) & 1;
    {   // q8: Delta=0b1100, canonical i: bit3==0, g=0b1000 -> p_i = 0 always
        GateP G = mkgate<true>(g2[8]);
        u64 b0 = F8 ? G.nb : G.bb, n0 = F8 ? G.bb : G.nb;
        #pragma unroll
        for (int i = 0; i < 8; i++) gpsel(w[i], w[i ^ 12], G.aa, b0, n0);
    }
    {   // q9: Delta=0b0110, canonical i: bit2==0, g=0b1100 -> p_i = bit3
        GateP G = mkgate<true>(g2[9]);
        u64 b0 = F9 ? G.nb : G.bb, n0 = F9 ? G.bb : G.nb;
        #pragma unroll
        for (int i = 0; i < 16; i++) if (!(i & 4)) {
            bool pr = (i & 8) != 0;
            gpsel(w[i], w[i ^ 6], G.aa, pr ? n0 : b0, pr ? b0 : n0);
        }
    }
    {   // q10: Delta=0b0011, canonical i: bit1==0, g=0b1110 -> p_i = bit3^bit2
        GateP G = mkgate<true>(g2[10]);
        u64 b0 = F10 ? G.nb : G.bb, n0 = F10 ? G.bb : G.nb;
        #pragma unroll
        for (int i = 0; i < 16; i++) if (!(i & 2)) {
            bool pr = (((i >> 3) ^ (i >> 2)) & 1) != 0;
            gpsel(w[i], w[i ^ 3], G.aa, pr ? n0 : b0, pr ? b0 : n0);
        }
    }
    {   // q11: Delta=0b0001, canonical i: bit0==0, g=0b1111 -> p_i = bit3^bit2^bit1
        GateP G = mkgate<true>(g2[11]);
        u64 b0 = F11 ? G.nb : G.bb, n0 = F11 ? G.bb : G.nb;
        #pragma unroll
        for (int i = 0; i < 16; i += 2) {
            bool pr = (((i >> 3) ^ (i >> 2) ^ (i >> 1)) & 1) != 0;
            gpsel(w[i], w[i ^ 1], G.aa, pr ? n0 : b0, pr ? b0 : n0);
        }
    }
    #pragma unroll
    for (int i = 0; i < 16; i++) {
        int off = ((i & 8) ? sA : 0) ^ ((i & 4) ? sB : 0) ^ ((i & 2) ? sC : 0) ^ ((i & 1) ? sD : 0);
        s[a0 ^ off] = w[i];
    }
}

__global__ void __launch_bounds__(NT)
vqc_kernel(const float* __restrict__ inputs,
           const float* __restrict__ thetas,
           float* __restrict__ out) {
    __shared__ float2 st[4096];
    __shared__ float4 vtab[12];   // column-0 of merged (enc + ansatz-L0) gate
    __shared__ float4 gtab[24];   // L1, L2 gate params (a, b, ph.x, ph.y)
    __shared__ u64   part[8][6];  // per-warp packed readout partials
    u64* s = reinterpret_cast<u64*>(st);

    const int tid = threadIdx.x;
    const int b   = blockIdx.x;

    // ---- per-qubit coefficients ----
    if (tid < 12) {
        int q = tid;
        float x  = inputs[b * 12 + q];
        float ty = thetas[2 * q], tz = thetas[2 * q + 1];
        float sx, cx, sy, cy, sz, cz;
        sincospif(x, &sx, &cx);            // e^{i pi x}
        sincospif(0.5f * ty, &sy, &cy);    // Y^ty entries
        sincospif(tz, &sz, &cz);           // e^{i pi tz}
        const float r = 0.70710678118654752f;
        // v = Z^tz * Y^ty * Z^x * H * (1,0)^T
        float v0x = r * (cy - sy * cx), v0y = -r * sy * sx;
        float tx = sy + cy * cx, tw = cy * sx;
        float v1x = r * (cz * tx - sz * tw), v1y = r * (cz * tw + sz * tx);
        vtab[q] = make_float4(v0x, v0y, v1x, v1y);
    } else if (tid < 36) {
        int idx = tid - 12;                 // (layer-1)*12 + q
        int l = idx / 12 + 1, q = idx % 12;
        float ty = thetas[l * 24 + 2 * q], tz = thetas[l * 24 + 2 * q + 1];
        float sy, cy, sz, cz;
        sincospif(0.5f * ty, &sy, &cy);
        sincospif(tz, &sz, &cz);
        // Layer 2 (idx >= 12): Z^tz diagonal & unobservable -> REAL passes ignore ph.
        gtab[idx] = make_float4(cy, -sy, cz, sz);
    }
    __syncthreads();

    // ---- init: product state after merged (enc + L0) layer, frame 0 ----
    {
        float4 v0q = vtab[0];
        float2 f = ((tid >> 7) & 1) ? hiF(v0q) : loF(v0q);
        #pragma unroll
        for (int q = 1; q < 8; q++) {
            float4 v = vtab[q];
            f = cmul(f, ((tid >> (7 - q)) & 1) ? hiF(v) : loF(v));
        }
        float4 v8 = vtab[8], v9 = vtab[9], vA = vtab[10], vB = vtab[11];
        float2 t8[2], t9[4], tA[8];
        t8[0] = cmul(f, loF(v8));  t8[1] = cmul(f, hiF(v8));
        #pragma unroll
        for (int j = 0; j < 2; j++) { t9[2*j] = cmul(t8[j], loF(v9)); t9[2*j+1] = cmul(t8[j], hiF(v9)); }
        #pragma unroll
        for (int j = 0; j < 4; j++) { tA[2*j] = cmul(t9[j], loF(vA)); tA[2*j+1] = cmul(t9[j], hiF(vA)); }
        #pragma unroll
        for (int l = 0; l < 16; l++) {
            float2 amp = cmul(tA[l >> 1], (l & 1) ? hiF(vB) : loF(vB));
            st[SW((tid << 4) | l)] = amp;
        }
    }
    __syncthreads();

    // ---- 5 passes: L1(q0-3), L1(q4-7), [L1(q8-11)+L2(q8-11)], L2(q0-3), L2(q4-7) ----
    u64 w[16];
    pass4<1, 0, true,  false>(s, gtab,      tid, w); __syncthreads();
    pass4<1, 4, true,  false>(s, gtab,      tid, w); __syncthreads();
    pass_fused(s, gtab, gtab + 12, tid, w);          __syncthreads();
    pass4<2, 0, true,  true >(s, gtab + 12, tid, w); __syncthreads();
    int b000 = pass4<2, 4, false, true>(s, gtab + 12, tid, w);  // + readout

    // ---- readout directly from registers ----
    // In-pass axes map to qubits 4..7 (bit3->q4, bit2->q5, bit1->q6, bit0->q7);
    // all other qubits have constant sign over the coset (from b000).
    float S = 0.f, d3 = 0.f, d2 = 0.f, d1 = 0.f, d0 = 0.f;
    #pragma unroll
    for (int i = 0; i < 16; i++) {
        float x, y; upk(w[i], x, y);
        float pr = fmaf(x, x, y * y);
        S += pr;
        d3 = (i & 8) ? d3 - pr : d3 + pr;
        d2 = (i & 4) ? d2 - pr : d2 + pr;
        d1 = (i & 2) ? d1 - pr : d1 + pr;
        d0 = (i & 1) ? d0 - pr : d0 + pr;
    }
    u64 acc[6];
    {
        float av[12];
        #pragma unroll
        for (int q = 0; q < 12; q++) {
            float v = (q == 4) ? d3 : (q == 5) ? d2 : (q == 6) ? d1 : (q == 7) ? d0 : S;
            av[q] = (__popc(b000 & ROWS2[q]) & 1) ? -v : v;
        }
        #pragma unroll
        for (int j = 0; j < 6; j++) acc[j] = pk(av[2*j], av[2*j+1]);
    }
    #pragma unroll
    for (int o = 16; o; o >>= 1) {
        #pragma unroll
        for (int j = 0; j < 6; j++)
            acc[j] = add2(acc[j], __shfl_xor_sync(0xffffffffu, acc[j], o));
    }
    if ((tid & 31) == 0) {
        #pragma unroll
        for (int j = 0; j < 6; j++) part[tid >> 5][j] = acc[j];
    }
    __syncthreads();
    if (tid < 12) {
        const float* pf = reinterpret_cast<const float*>(part);
        float r0 = 0.f;
        #pragma unroll
        for (int wgt = 0; wgt < 8; wgt++) r0 += pf[wgt * 12 + tid];
        out[b * 12 + tid] = r0;
    }
}

extern "C" void kernel_launch(void* const* d_in, const int* in_sizes, int n_in,
                              void* d_out, int out_size) {
    const float* inputs = (const float*)d_in[0];   // [1024, 12] f32
    const float* thetas = (const float*)d_in[1];   // [72] f32
    float* out = (float*)d_out;                    // [1024, 12] f32
    vqc_kernel<<<1024, NT>>>(inputs, thetas, out);
}